// round 7
// baseline (speedup 1.0000x reference)
#include <cuda_runtime.h>
#include <cuda_bf16.h>
#include <math.h>

#define BATCH 8
#define DIM 96
#define HH 192
#define WW 192
#define NEXP 6
#define TOPK 3

typedef unsigned long long u64;

// ---------- packed f32x2 helpers (sm_103a) ----------
__device__ __forceinline__ u64 pk2(float lo, float hi) {
    u64 d; asm("mov.b64 %0, {%1, %2};" : "=l"(d) : "f"(lo), "f"(hi)); return d;
}
__device__ __forceinline__ void upk2(u64 d, float& lo, float& hi) {
    asm("mov.b64 {%0, %1}, %2;" : "=f"(lo), "=f"(hi) : "l"(d));
}
__device__ __forceinline__ u64 fma2(u64 a, u64 b, u64 c) {
    u64 d; asm("fma.rn.f32x2 %0, %1, %2, %3;" : "=l"(d) : "l"(a), "l"(b), "l"(c)); return d;
}
__device__ __forceinline__ u64 add2(u64 a, u64 b) {
    u64 d; asm("add.rn.f32x2 %0, %1, %2;" : "=l"(d) : "l"(a), "l"(b)); return d;
}

// ---------- device scratch ----------
__device__ float g_pooled[BATCH * DIM];
__device__ int   g_idx[BATCH * TOPK];
__device__ float g_w[BATCH * TOPK];

// ---------------------------------------------------------------
// Kernel A: per-(b,c) max+mean pooling over HxW
// ---------------------------------------------------------------
__global__ __launch_bounds__(256) void pool_kernel(const float* __restrict__ x) {
    int bc = blockIdx.x;
    const float4* p4 = reinterpret_cast<const float4*>(x + (size_t)bc * (HH * WW));
    float mx = -1e30f, sm = 0.f;
    for (int i = threadIdx.x; i < (HH * WW / 4); i += 256) {
        float4 v = p4[i];
        mx = fmaxf(mx, fmaxf(fmaxf(v.x, v.y), fmaxf(v.z, v.w)));
        sm += (v.x + v.y) + (v.z + v.w);
    }
#pragma unroll
    for (int o = 16; o; o >>= 1) {
        mx = fmaxf(mx, __shfl_xor_sync(0xffffffffu, mx, o));
        sm += __shfl_xor_sync(0xffffffffu, sm, o);
    }
    __shared__ float smx[8], ssm[8];
    int w = threadIdx.x >> 5, l = threadIdx.x & 31;
    if (l == 0) { smx[w] = mx; ssm[w] = sm; }
    __syncthreads();
    if (threadIdx.x == 0) {
        float M = smx[0], S = ssm[0];
#pragma unroll
        for (int i = 1; i < 8; i++) { M = fmaxf(M, smx[i]); S += ssm[i]; }
        g_pooled[bc] = M + S * (1.0f / (HH * WW));
    }
}

// ---------------------------------------------------------------
// Kernel B: gate
// ---------------------------------------------------------------
__global__ __launch_bounds__(64) void gate_kernel(const float* __restrict__ w_fc0,
                                                  const float* __restrict__ b_fc0,
                                                  const float* __restrict__ w_fc1,
                                                  const float* __restrict__ b_fc1) {
    __shared__ float sh_g[BATCH][NEXP], sh_nz[BATCH][NEXP];
    int t = threadIdx.x;
    if (t < BATCH * NEXP) {
        int b = t / NEXP, e = t - b * NEXP;
        const float* p = g_pooled + b * DIM;
        float d0 = b_fc0[e], d1 = b_fc1[e];
        for (int c = 0; c < DIM; c++) {
            float pv = p[c];
            d0 = fmaf(pv, w_fc0[e * DIM + c], d0);
            d1 = fmaf(pv, w_fc1[e * DIM + c], d1);
        }
        sh_g[b][e]  = (d1 >= 0.f) ? d1 : 0.2f * d1;
        sh_nz[b][e] = fmaxf(d0, 0.f) + log1pf(expf(-fabsf(d0)));
    }
    __syncthreads();
    if (t < BATCH) {
        int b = t;
        float g[NEXP], nz[NEXP];
#pragma unroll
        for (int e = 0; e < NEXP; e++) { g[e] = sh_g[b][e]; nz[e] = sh_nz[b][e]; }
        float mu = 0.f;
#pragma unroll
        for (int e = 0; e < NEXP; e++) mu += nz[e];
        mu *= (1.0f / NEXP);
        float var = 0.f;
#pragma unroll
        for (int e = 0; e < NEXP; e++) { float d = nz[e] - mu; var += d * d; }
        float sd = sqrtf(var / (NEXP - 1));
        float sc[NEXP];
#pragma unroll
        for (int e = 0; e < NEXP; e++) sc[e] = g[e] + (nz[e] - mu) / sd;

        bool used[NEXP] = {false, false, false, false, false, false};
        int idx[TOPK];
#pragma unroll
        for (int k = 0; k < TOPK; k++) {
            float best = -1e30f; int bi = 0;
#pragma unroll
            for (int e = 0; e < NEXP; e++)
                if (!used[e] && sc[e] > best) { best = sc[e]; bi = e; }
            used[bi] = true;
            idx[k] = bi;
        }
        float m = fmaxf(g[idx[0]], fmaxf(g[idx[1]], g[idx[2]]));
        float ex[TOPK], s = 0.f;
#pragma unroll
        for (int k = 0; k < TOPK; k++) { ex[k] = expf(g[idx[k]] - m); s += ex[k]; }
        float inv = 1.0f / s;
#pragma unroll
        for (int k = 0; k < TOPK; k++) {
            g_idx[b * TOPK + k] = idx[k];
            g_w[b * TOPK + k]   = ex[k] * inv;
        }
    }
}

// ---------------------------------------------------------------
// Kernel C: fused conv1 -> relu -> conv2 -> weighted sum (f32x2)
// 96 threads, thread t owns output column pair (2t, 2t+1), 16-row tile.
// in_s: col j at float idx j+1 (R4 layout, window = 2 aligned LDS.64).
// c1:   even/odd split arrays, all stores/loads conflict-free stride-1.
// ---------------------------------------------------------------
#define INW 196
#define INW2 98
#define C1P 100   // padded row stride (floats) for c1 even/odd arrays

struct P3 { u64 p0, p1, p2; };

__device__ __forceinline__ P3 load3_in(const float2* row, int t) {
    float2 L = row[t];       // cols (2t-1, 2t)
    float2 R = row[t + 1];   // cols (2t+1, 2t+2)
    P3 r;
    r.p0 = pk2(L.x, L.y);
    r.p1 = pk2(L.y, R.x);
    r.p2 = pk2(R.x, R.y);
    return r;
}

// conv1 + relu into even/odd c1 arrays. EDGE masks out-of-image rows to 0.
template <bool EDGE>
__device__ __forceinline__ void conv1_pass(const float2* in2,
                                           float* c1e, float* c1o,
                                           const float* __restrict__ w1, float bias1,
                                           int t, int h0) {
    const u64 K0 = pk2(w1[0], w1[0]), K1 = pk2(w1[1], w1[1]), K2 = pk2(w1[2], w1[2]);
    const u64 K3 = pk2(w1[3], w1[3]), K4 = pk2(w1[4], w1[4]), K5 = pk2(w1[5], w1[5]);
    const u64 K6 = pk2(w1[6], w1[6]), K7 = pk2(w1[7], w1[7]), K8 = pk2(w1[8], w1[8]);
    const u64 B1 = pk2(bias1, bias1);

    P3 A = load3_in(in2 + 0 * INW2, t);
    P3 B = load3_in(in2 + 1 * INW2, t);
#pragma unroll
    for (int r = 0; r < 18; r++) {
        P3 C = load3_in(in2 + (r + 2) * INW2, t);
        u64 v = fma2(K0, A.p0, fma2(K1, A.p1, fma2(K2, A.p2,
                fma2(K3, B.p0, fma2(K4, B.p1, fma2(K5, B.p2,
                fma2(K6, C.p0, fma2(K7, C.p1, fma2(K8, C.p2, B1)))))))));
        float v0, v1; upk2(v, v0, v1);
        float r0 = fmaxf(v0, 0.f), r1 = fmaxf(v1, 0.f);
        if (EDGE) {
            const int hr = h0 + r - 1;
            const bool hok = (unsigned)hr < (unsigned)HH;
            r0 = hok ? r0 : 0.f;
            r1 = hok ? r1 : 0.f;
        }
        c1e[r * C1P + t]     = r0;   // col 2t    -> stride-1, conflict-free
        c1o[r * C1P + t + 1] = r1;   // col 2t+1  -> stride-1, conflict-free
        A = B; B = C;
    }
}

__global__ __launch_bounds__(96) void moe_kernel(
    const float* __restrict__ x,
    const float* __restrict__ ew1, const float* __restrict__ eb1,
    const float* __restrict__ ew2, const float* __restrict__ eb2,
    float* __restrict__ out)
{
    const int t  = threadIdx.x;             // 0..95, column pair (2t, 2t+1)
    const int h0 = blockIdx.x * 16;
    const int c  = blockIdx.y;
    const int b  = blockIdx.z;
    const bool vedge = (h0 == 0) || (h0 + 16 == HH);

    // x tile: rows h0-2..h0+17 (20), col j at idx j+1; idx 0 & 193 are zero pad
    __shared__ __align__(16) float in_s[20 * INW];
    // relu(conv1): even cols c1e[r][i]=col 2i (i=0..95, slot 96 = col192 = 0)
    //              odd  cols c1o[r][i]=col 2i-1 (i=1..96, slot 0 = col -1 = 0)
    __shared__ float c1e[18 * C1P];
    __shared__ float c1o[18 * C1P];

    // ---- vectorized tile load: 20 row passes, 1 coalesced float2 each ----
    const float* xp = x + (size_t)(b * DIM + c) * (HH * WW);
#pragma unroll 4
    for (int ri = 0; ri < 20; ri++) {
        const int h = h0 - 2 + ri;
        float2 v = make_float2(0.f, 0.f);
        if ((unsigned)h < (unsigned)HH)
            v = reinterpret_cast<const float2*>(xp + h * WW)[t];
        in_s[ri * INW + 2 * t + 1] = v.x;
        in_s[ri * INW + 2 * t + 2] = v.y;
        if (t == 0) { in_s[ri * INW + 0] = 0.f; in_s[ri * INW + 193] = 0.f; }
    }
    // zero halo slots of c1 arrays (never written by conv1)
    if (t < 18) { c1e[t * C1P + 96] = 0.f; c1o[t * C1P + 0] = 0.f; }

    u64 acc[16];
#pragma unroll
    for (int r = 0; r < 16; r++) acc[r] = 0ull;
    __syncthreads();

    const float2* in2 = reinterpret_cast<const float2*>(in_s);

    for (int ki = 0; ki < TOPK; ki++) {
        const int   e   = g_idx[b * TOPK + ki];
        const float cof = g_w[b * TOPK + ki];
        const float* w1 = ew1 + ((size_t)e * DIM + c) * 9;
        const float* w2 = ew2 + ((size_t)e * DIM + c) * 9;

        if (vedge)
            conv1_pass<true >(in2, c1e, c1o, w1, eb1[e * DIM + c], t, h0);
        else
            conv1_pass<false>(in2, c1e, c1o, w1, eb1[e * DIM + c], t, h0);
        __syncthreads();

        // ---- conv2 (weights pre-scaled by gate coeff), accumulate ----
        {
            const u64 S0 = pk2(cof * w2[0], cof * w2[0]), S1 = pk2(cof * w2[1], cof * w2[1]);
            const u64 S2 = pk2(cof * w2[2], cof * w2[2]), S3 = pk2(cof * w2[3], cof * w2[3]);
            const u64 S4 = pk2(cof * w2[4], cof * w2[4]), S5 = pk2(cof * w2[5], cof * w2[5]);
            const u64 S6 = pk2(cof * w2[6], cof * w2[6]), S7 = pk2(cof * w2[7], cof * w2[7]);
            const u64 S8 = pk2(cof * w2[8], cof * w2[8]);
            float bbv = cof * eb2[e * DIM + c];
            const u64 BB = pk2(bbv, bbv);

            // rolling 3-row window of packed taps built from even/odd arrays
            P3 A, B;
            {
                float o0 = c1o[0 * C1P + t], e0 = c1e[0 * C1P + t];
                float o1 = c1o[0 * C1P + t + 1], e1 = c1e[0 * C1P + t + 1];
                A.p0 = pk2(o0, e0); A.p1 = pk2(e0, o1); A.p2 = pk2(o1, e1);
                float q0 = c1o[1 * C1P + t], f0 = c1e[1 * C1P + t];
                float q1 = c1o[1 * C1P + t + 1], f1 = c1e[1 * C1P + t + 1];
                B.p0 = pk2(q0, f0); B.p1 = pk2(f0, q1); B.p2 = pk2(q1, f1);
            }
#pragma unroll
            for (int r = 0; r < 16; r++) {
                P3 C;
                {
                    float o0 = c1o[(r + 2) * C1P + t], e0 = c1e[(r + 2) * C1P + t];
                    float o1 = c1o[(r + 2) * C1P + t + 1], e1 = c1e[(r + 2) * C1P + t + 1];
                    C.p0 = pk2(o0, e0); C.p1 = pk2(e0, o1); C.p2 = pk2(o1, e1);
                }
                acc[r] = fma2(S0, A.p0, fma2(S1, A.p1, fma2(S2, A.p2,
                         fma2(S3, B.p0, fma2(S4, B.p1, fma2(S5, B.p2,
                         fma2(S6, C.p0, fma2(S7, C.p1, fma2(S8, C.p2,
                         add2(acc[r], BB))))))))));
                A = B; B = C;
            }
        }
        __syncthreads();
    }

    float* op = out + (size_t)(b * DIM + c) * (HH * WW) + h0 * WW + 2 * t;
#pragma unroll
    for (int r = 0; r < 16; r++) {
        float o0, o1; upk2(acc[r], o0, o1);
        reinterpret_cast<float2*>(op + r * WW)[0] = make_float2(o0, o1);
    }
}

// ---------------------------------------------------------------
extern "C" void kernel_launch(void* const* d_in, const int* in_sizes, int n_in,
                              void* d_out, int out_size) {
    const float* x     = (const float*)d_in[0];
    const float* w_fc0 = (const float*)d_in[1];
    const float* b_fc0 = (const float*)d_in[2];
    const float* w_fc1 = (const float*)d_in[3];
    const float* b_fc1 = (const float*)d_in[4];
    const float* ew1   = (const float*)d_in[5];
    const float* eb1   = (const float*)d_in[6];
    const float* ew2   = (const float*)d_in[7];
    const float* eb2   = (const float*)d_in[8];
    float* out = (float*)d_out;

    pool_kernel<<<BATCH * DIM, 256>>>(x);
    gate_kernel<<<1, 64>>>(w_fc0, b_fc0, w_fc1, b_fc1);
    dim3 grid(HH / 16, DIM, BATCH);
    moe_kernel<<<grid, 96>>>(x, ew1, eb1, ew2, eb2, out);
}